// round 3
// baseline (speedup 1.0000x reference)
#include <cuda_runtime.h>
#include <math.h>

#define S_LEN  512
#define BATCH  4
#define NHEAD  16
#define DHEAD  64
#define DMODEL 1024
#define D3     3072
#define NTOK   2048   // BATCH * S_LEN

// ---------------- scratch (static device globals; no allocation) ----------------
__device__ float g_qkv_r[NTOK * D3];       // 25.2 MB
__device__ float g_qkv_i[NTOK * D3];
__device__ float g_attn_r[NTOK * DMODEL];  // 8.4 MB
__device__ float g_attn_i[NTOK * DMODEL];
__device__ float g_rc[S_LEN * DHEAD];
__device__ float g_rs[S_LEN * DHEAD];

// ---------------- RoPE rotor table ----------------
__global__ void rope_table_kernel() {
    int s = blockIdx.x, d = threadIdx.x;
    float inv = powf(10000.0f, -((float)d) / 64.0f);
    float ang = (float)s * inv;
    g_rc[s * DHEAD + d] = cosf(ang);
    g_rs[s * DHEAD + d] = sinf(ang);
}

// ---------------- complex GEMM: C = A * B^T (A:[M,K], B:[N,K], row-major) -------
// acc_r = Ar*Br - Ai*Bi ; acc_i = Ar*Bi + Ai*Br
__global__ __launch_bounds__(256)
void cgemm_nt_kernel(const float* __restrict__ Ar, const float* __restrict__ Ai,
                     const float* __restrict__ Br, const float* __restrict__ Bi,
                     float* __restrict__ Cr, float* __restrict__ Ci,
                     int N, int K)
{
    const int BM = 64, BN = 64, BK = 16;
    __shared__ float As_r[BK][BM + 1];
    __shared__ float As_i[BK][BM + 1];
    __shared__ float Bs_r[BK][BN + 1];
    __shared__ float Bs_i[BK][BN + 1];

    int tid = threadIdx.x;
    int tx = tid & 15;       // 0..15 -> n micro
    int ty = tid >> 4;       // 0..15 -> m micro
    int m0 = blockIdx.y * BM;
    int n0 = blockIdx.x * BN;

    int lrow = tid >> 2;          // 0..63
    int lk   = (tid & 3) * 4;     // 0,4,8,12

    float acc_r[4][4];
    float acc_i[4][4];
#pragma unroll
    for (int i = 0; i < 4; i++)
#pragma unroll
        for (int j = 0; j < 4; j++) { acc_r[i][j] = 0.f; acc_i[i][j] = 0.f; }

    for (int k0 = 0; k0 < K; k0 += BK) {
        float4 a_r = *(const float4*)(Ar + (size_t)(m0 + lrow) * K + k0 + lk);
        float4 a_i = *(const float4*)(Ai + (size_t)(m0 + lrow) * K + k0 + lk);
        float4 b_r = *(const float4*)(Br + (size_t)(n0 + lrow) * K + k0 + lk);
        float4 b_i = *(const float4*)(Bi + (size_t)(n0 + lrow) * K + k0 + lk);

        As_r[lk + 0][lrow] = a_r.x; As_r[lk + 1][lrow] = a_r.y;
        As_r[lk + 2][lrow] = a_r.z; As_r[lk + 3][lrow] = a_r.w;
        As_i[lk + 0][lrow] = a_i.x; As_i[lk + 1][lrow] = a_i.y;
        As_i[lk + 2][lrow] = a_i.z; As_i[lk + 3][lrow] = a_i.w;
        Bs_r[lk + 0][lrow] = b_r.x; Bs_r[lk + 1][lrow] = b_r.y;
        Bs_r[lk + 2][lrow] = b_r.z; Bs_r[lk + 3][lrow] = b_r.w;
        Bs_i[lk + 0][lrow] = b_i.x; Bs_i[lk + 1][lrow] = b_i.y;
        Bs_i[lk + 2][lrow] = b_i.z; Bs_i[lk + 3][lrow] = b_i.w;
        __syncthreads();

#pragma unroll
        for (int kk = 0; kk < BK; kk++) {
            float xr[4], xi[4], yr[4], yi[4];
#pragma unroll
            for (int i = 0; i < 4; i++) {
                xr[i] = As_r[kk][ty * 4 + i];
                xi[i] = As_i[kk][ty * 4 + i];
            }
#pragma unroll
            for (int j = 0; j < 4; j++) {
                yr[j] = Bs_r[kk][tx * 4 + j];
                yi[j] = Bs_i[kk][tx * 4 + j];
            }
#pragma unroll
            for (int i = 0; i < 4; i++)
#pragma unroll
                for (int j = 0; j < 4; j++) {
                    acc_r[i][j] = fmaf(xr[i], yr[j], fmaf(-xi[i], yi[j], acc_r[i][j]));
                    acc_i[i][j] = fmaf(xr[i], yi[j], fmaf(xi[i], yr[j], acc_i[i][j]));
                }
        }
        __syncthreads();
    }

#pragma unroll
    for (int i = 0; i < 4; i++) {
        size_t row = (size_t)(m0 + ty * 4 + i) * N + n0 + tx * 4;
#pragma unroll
        for (int j = 0; j < 4; j++) {
            Cr[row + j] = acc_r[i][j];
            Ci[row + j] = acc_i[i][j];
        }
    }
}

// ---------------- in-place RoPE on Q,K columns of qkv ----------------
__global__ __launch_bounds__(256)
void rope_apply_kernel(float* __restrict__ qr, float* __restrict__ qi) {
    int t = blockIdx.x;          // token 0..2047
    int s = t & (S_LEN - 1);
    size_t base = (size_t)t * D3;
    for (int c = threadIdx.x; c < 2 * DMODEL; c += 256) {
        int d = c & (DHEAD - 1);
        float co = g_rc[s * DHEAD + d];
        float si = g_rs[s * DHEAD + d];
        float xr = qr[base + c];
        float xi = qi[base + c];
        qr[base + c] = xr * co - xi * si;
        qi[base + c] = xr * si + xi * co;
    }
}

// ---------------- fused attention: one block per (b, h, q-row) ----------------
__global__ __launch_bounds__(128)
void attn_kernel(const float* __restrict__ qkv_r, const float* __restrict__ qkv_i,
                 float* __restrict__ out_r, float* __restrict__ out_i)
{
    int q = blockIdx.x;
    int h = blockIdx.y;
    int b = blockIdx.z;
    int tid = threadIdx.x;  // 128

    __shared__ float q_r[DHEAD], q_i[DHEAD];
    __shared__ float s_re[S_LEN];   // scores re -> exp -> w_cos
    __shared__ float s_im[S_LEN];   // scores im -> w_sin
    __shared__ float red[128];

    const size_t tok_base = (size_t)b * S_LEN;

    // load rotated Q row
    if (tid < DHEAD) {
        size_t off = (tok_base + q) * D3 + h * DHEAD + tid;
        q_r[tid] = qkv_r[off];
        q_i[tid] = qkv_i[off];
    }
    __syncthreads();

    const float scale = 0.125f;  // 1/sqrt(64)

    // scores
    for (int k = tid; k < S_LEN; k += 128) {
        const float4* kr4 = (const float4*)(qkv_r + (tok_base + k) * D3 + DMODEL + h * DHEAD);
        const float4* ki4 = (const float4*)(qkv_i + (tok_base + k) * D3 + DMODEL + h * DHEAD);
        float re = 0.f, im = 0.f;
#pragma unroll
        for (int dv = 0; dv < 16; dv++) {
            float4 a = kr4[dv];
            float4 c = ki4[dv];
            int d = dv * 4;
            re += q_r[d + 0] * a.x + q_i[d + 0] * c.x;
            im += q_i[d + 0] * a.x - q_r[d + 0] * c.x;
            re += q_r[d + 1] * a.y + q_i[d + 1] * c.y;
            im += q_i[d + 1] * a.y - q_r[d + 1] * c.y;
            re += q_r[d + 2] * a.z + q_i[d + 2] * c.z;
            im += q_i[d + 2] * a.z - q_r[d + 2] * c.z;
            re += q_r[d + 3] * a.w + q_i[d + 3] * c.w;
            im += q_i[d + 3] * a.w - q_r[d + 3] * c.w;
        }
        s_re[k] = re * scale;
        s_im[k] = im * scale;
    }
    __syncthreads();

    // softmax(re)
    float lmax = -1e30f;
    for (int k = tid; k < S_LEN; k += 128) lmax = fmaxf(lmax, s_re[k]);
    red[tid] = lmax;
    __syncthreads();
    for (int o = 64; o > 0; o >>= 1) {
        if (tid < o) red[tid] = fmaxf(red[tid], red[tid + o]);
        __syncthreads();
    }
    float mx = red[0];
    __syncthreads();

    float lsum = 0.f;
    for (int k = tid; k < S_LEN; k += 128) {
        float e = __expf(s_re[k] - mx);
        s_re[k] = e;
        lsum += e;
    }
    red[tid] = lsum;
    __syncthreads();
    for (int o = 64; o > 0; o >>= 1) {
        if (tid < o) red[tid] += red[tid + o];
        __syncthreads();
    }
    float inv = 1.0f / red[0];
    __syncthreads();

    // weights: w_cos = p*cos(im), w_sin = p*sin(im)
    for (int k = tid; k < S_LEN; k += 128) {
        float p = s_re[k] * inv;
        float sv, cv;
        sincosf(s_im[k], &sv, &cv);
        s_re[k] = p * cv;
        s_im[k] = p * sv;
    }
    __syncthreads();

    // output: threads 0..63 -> real part for dim d; 64..127 -> imag part
    int d = tid & (DHEAD - 1);
    bool imag = tid >= DHEAD;
    const float* vr = qkv_r + tok_base * D3 + 2 * DMODEL + h * DHEAD + d;
    const float* vi = qkv_i + tok_base * D3 + 2 * DMODEL + h * DHEAD + d;
    float acc = 0.f;
#pragma unroll 8
    for (int k = 0; k < S_LEN; k++) {
        float wc = s_re[k];
        float ws = s_im[k];
        float Vr = vr[(size_t)k * D3];
        float Vi = vi[(size_t)k * D3];
        acc += imag ? (wc * Vi + ws * Vr) : (wc * Vr - ws * Vi);
    }
    size_t o = (tok_base + q) * DMODEL + h * DHEAD + d;
    if (imag) out_i[o] = acc;
    else      out_r[o] = acc;
}

// ---------------- launch ----------------
extern "C" void kernel_launch(void* const* d_in, const int* in_sizes, int n_in,
                              void* d_out, int out_size)
{
    const float* x_re    = (const float*)d_in[0];
    const float* x_im    = (const float*)d_in[1];
    const float* wqkv_re = (const float*)d_in[2];
    const float* wqkv_im = (const float*)d_in[3];
    const float* wo_re   = (const float*)d_in[4];
    const float* wo_im   = (const float*)d_in[5];
    float* out = (float*)d_out;

    float *qkv_r, *qkv_i, *attn_r, *attn_i;
    cudaGetSymbolAddress((void**)&qkv_r,  g_qkv_r);
    cudaGetSymbolAddress((void**)&qkv_i,  g_qkv_i);
    cudaGetSymbolAddress((void**)&attn_r, g_attn_r);
    cudaGetSymbolAddress((void**)&attn_i, g_attn_i);

    // 1. RoPE rotor table
    rope_table_kernel<<<S_LEN, DHEAD>>>();

    // 2. complex QKV projection: [2048,1024] x [3072,1024]^T
    dim3 g1(D3 / 64, NTOK / 64);
    cgemm_nt_kernel<<<g1, 256>>>(x_re, x_im, wqkv_re, wqkv_im, qkv_r, qkv_i, D3, DMODEL);

    // 3. RoPE applied in place to Q and K columns
    rope_apply_kernel<<<NTOK, 256>>>(qkv_r, qkv_i);

    // 4. fused attention (q varies fastest -> K/V L2 reuse within (b,h))
    dim3 g2(S_LEN, NHEAD, BATCH);
    attn_kernel<<<g2, 128>>>(qkv_r, qkv_i, attn_r, attn_i);

    // 5. complex output projection straight into d_out ([2,B,S,D])
    dim3 g3(DMODEL / 64, NTOK / 64);
    cgemm_nt_kernel<<<g3, 256>>>(attn_r, attn_i, wo_re, wo_im,
                                 out, out + (size_t)NTOK * DMODEL, DMODEL, DMODEL);
}